// round 8
// baseline (speedup 1.0000x reference)
#include <cuda_runtime.h>
#include <cuda_fp16.h>
#include <mma.h>
#include <cstdint>

using namespace nvcuda;

// Problem constants
#define BB 2
#define NN 10000
#define MM 320000
#define DD 256
#define HH 8
#define ROWS (BB * NN)          // 20000 flattened GEMM rows
#define MPAD 20096              // 157 * 128 tiles
#define TOTAL_E (BB * MM)       // 640000 (b, edge) pairs
#define BK 32
#define LDA 40                  // As padded stride (halves): 80B, conflict-free LDSM
#define LDB 136                 // Bs padded stride (halves): 272B, conflict-free LDSM
#define LDS_STAGE 20            // epilogue staging stride (floats)

// ---------------- scratch (device globals; no allocation allowed) ----------
__device__ __half g_wh[2 * DD * DD];            // fp16 w_q | w_k
__device__ __half g_qh[(size_t)MPAD * DD];      // fp16 q
__device__ __half g_kh[(size_t)MPAD * DD];      // fp16 k
__device__ float  g_seg[(size_t)BB * NN * HH];  // 640 KB
__device__ int    g_mask32[2 * MM];             // canonical int32 mask
__device__ int    g_is64;                       // detected mask dtype
__device__ int    g_bin[NN];                    // histogram -> start offsets
__device__ int    g_cursor[NN];                 // scatter cursors
__device__ int    g_perm[MM];                   // edges sorted by i0

// ---------------- K_pre0: detect mask dtype ---------------------------------
__global__ void detect_mask_kernel(const unsigned* __restrict__ mraw) {
    __shared__ int any_nonzero;
    if (threadIdx.x == 0) any_nonzero = 0;
    __syncthreads();
    unsigned v = mraw[threadIdx.x * 2 + 1];
    if (v != 0u) atomicOr(&any_nonzero, 1);
    __syncthreads();
    if (threadIdx.x == 0) g_is64 = any_nonzero ? 0 : 1;
}

// ---------------- K_pre1: normalize mask; zero seg + histogram --------------
__global__ void convert_mask_kernel(const void* __restrict__ mraw) {
    int t = blockIdx.x * blockDim.x + threadIdx.x;
    if (t < 2 * MM) {
        long long v;
        if (g_is64) v = ((const long long*)mraw)[t];
        else        v = (long long)((const int*)mraw)[t];
        int vi = (int)v;
        vi = vi < 0 ? 0 : (vi >= NN ? NN - 1 : vi);
        g_mask32[t] = vi;
    }
    if (t < BB * NN * HH) g_seg[t] = 0.0f;
    if (t < NN) g_bin[t] = 0;
}

// ---------------- K_pre2: fp32 -> fp16 conversion of weights only -----------
__global__ void convert_weights_kernel(const float* __restrict__ wq,
                                       const float* __restrict__ wk) {
    const int t = blockIdx.x * blockDim.x + threadIdx.x;
    const int per_mat = DD * DD / 8;
    if (t >= 2 * per_mat) return;
    const int mat = t / per_mat;
    const int e   = (t % per_mat) * 8;
    const float* src = (mat == 0 ? wq : wk) + e;
    float4 f0 = *(const float4*)(src);
    float4 f1 = *(const float4*)(src + 4);
    __half2 h[4];
    h[0] = __float22half2_rn(make_float2(f0.x, f0.y));
    h[1] = __float22half2_rn(make_float2(f0.z, f0.w));
    h[2] = __float22half2_rn(make_float2(f1.x, f1.y));
    h[3] = __float22half2_rn(make_float2(f1.z, f1.w));
    *(uint4*)(g_wh + (size_t)mat * DD * DD + e) = *(uint4*)h;
}

// ---------------- sort K_s1: histogram of i0 --------------------------------
__global__ void hist_kernel() {
    int t = blockIdx.x * blockDim.x + threadIdx.x;
    if (t < MM) atomicAdd(&g_bin[g_mask32[t]], 1);
}

// ---------------- sort K_s2: exclusive prefix scan (one block) --------------
__global__ void prefix_kernel() {
    __shared__ int partial[256];
    const int tid = threadIdx.x;
    const int per = (NN + 255) / 256;   // 40
    const int base = tid * per;
    int sum = 0;
    for (int i = 0; i < per; i++) {
        int idx = base + i;
        if (idx < NN) sum += g_bin[idx];
    }
    partial[tid] = sum;
    __syncthreads();
    // Hillis-Steele inclusive scan over 256 partials
    for (int s = 1; s < 256; s <<= 1) {
        int v = (tid >= s) ? partial[tid - s] : 0;
        __syncthreads();
        partial[tid] += v;
        __syncthreads();
    }
    int off = partial[tid] - sum;       // exclusive offset for this chunk
    for (int i = 0; i < per; i++) {
        int idx = base + i;
        if (idx < NN) {
            int v = g_bin[idx];
            g_bin[idx]    = off;        // start offset
            g_cursor[idx] = off;
            off += v;
        }
    }
}

// ---------------- sort K_s3: scatter edge ids into sorted order -------------
__global__ void scatter_kernel() {
    int t = blockIdx.x * blockDim.x + threadIdx.x;
    if (t >= MM) return;
    int i0 = g_mask32[t];
    int pos = atomicAdd(&g_cursor[i0], 1);
    g_perm[pos] = t;
}

// ---------------- K1: HMMA GEMM  C = A(fp32->fp16) * W(fp16) ----------------
// BM=128, BN=128, BK=32; 8 warps 4x2, 2x4 wmma frags each. A read directly as
// fp32 (conversion fused into smem store). OOB rows clamp to ROWS-1 (pad rows
// of C get garbage; never read). Padded smem strides; register prefetch.
__global__ void __launch_bounds__(256, 2)
gemm_wmma_kernel(const float* __restrict__ xq, const float* __restrict__ xk) {
    const int mat = blockIdx.z;
    const float*  A = (mat == 0) ? xq : xk;
    const __half* B = g_wh + (size_t)mat * DD * DD;
    __half*       C = (mat == 0) ? g_qh : g_kh;

    __shared__ __half As[128 * LDA];            // padded: 10 KB
    __shared__ __half Bs[BK * LDB];             // padded: 8.5 KB
    __shared__ float  stage[8][16 * LDS_STAGE]; // per-warp staging, 10 KB

    const int tid  = threadIdx.x;
    const int warp = tid >> 5;
    const int lane = tid & 31;
    const int wm = warp >> 1;
    const int wn = warp & 1;
    const int block_row = blockIdx.x * 128;
    const int block_col = blockIdx.y * 128;

    // A: two passes of 256 threads; each thread loads 8 fp32 (row idx>>2,
    // float-col (idx&3)*8 within the 32-wide k-slice)
    const int a_r0 = tid >> 2;          // 0..63
    const int a_r1 = a_r0 + 64;         // 64..127
    const int a_cf = (tid & 3) * 8;     // 0,8,16,24
    const int gr0 = min(block_row + a_r0, ROWS - 1);
    const int gr1 = min(block_row + a_r1, ROWS - 1);
    const float* a_src0 = A + (size_t)gr0 * DD + a_cf;
    const float* a_src1 = A + (size_t)gr1 * DD + a_cf;

    const int b_r0 = tid >> 4,          b_c0 = (tid & 15) * 8;
    const int b_r1 = (tid + 256) >> 4,  b_c1 = ((tid + 256) & 15) * 8;
    const __half* b_src0 = B + (size_t)b_r0 * DD + block_col + b_c0;
    const __half* b_src1 = B + (size_t)b_r1 * DD + block_col + b_c1;

    wmma::fragment<wmma::accumulator, 16, 16, 16, float> acc[2][4];
    #pragma unroll
    for (int i = 0; i < 2; i++)
        #pragma unroll
        for (int j = 0; j < 4; j++) wmma::fill_fragment(acc[i][j], 0.0f);

    // prefetch k0 = 0
    float4 a00 = *(const float4*)(a_src0);
    float4 a01 = *(const float4*)(a_src0 + 4);
    float4 a10 = *(const float4*)(a_src1);
    float4 a11 = *(const float4*)(a_src1 + 4);
    uint4  bv0 = *(const uint4*)(b_src0);
    uint4  bv1 = *(const uint4*)(b_src1);

    for (int k0 = 0; k0 < DD; k0 += BK) {
        {   // convert fp32 -> fp16 and stage A
            __half2 h0[4], h1[4];
            h0[0] = __float22half2_rn(make_float2(a00.x, a00.y));
            h0[1] = __float22half2_rn(make_float2(a00.z, a00.w));
            h0[2] = __float22half2_rn(make_float2(a01.x, a01.y));
            h0[3] = __float22half2_rn(make_float2(a01.z, a01.w));
            h1[0] = __float22half2_rn(make_float2(a10.x, a10.y));
            h1[1] = __float22half2_rn(make_float2(a10.z, a10.w));
            h1[2] = __float22half2_rn(make_float2(a11.x, a11.y));
            h1[3] = __float22half2_rn(make_float2(a11.z, a11.w));
            *(uint4*)(As + a_r0 * LDA + a_cf) = *(uint4*)h0;
            *(uint4*)(As + a_r1 * LDA + a_cf) = *(uint4*)h1;
        }
        *(uint4*)(Bs + b_r0 * LDB + b_c0) = bv0;
        *(uint4*)(Bs + b_r1 * LDB + b_c1) = bv1;
        __syncthreads();

        if (k0 + BK < DD) {             // issue next tile's loads early
            a00 = *(const float4*)(a_src0 + k0 + BK);
            a01 = *(const float4*)(a_src0 + k0 + BK + 4);
            a10 = *(const float4*)(a_src1 + k0 + BK);
            a11 = *(const float4*)(a_src1 + k0 + BK + 4);
            bv0 = *(const uint4*)(b_src0 + (size_t)(k0 + BK) * DD);
            bv1 = *(const uint4*)(b_src1 + (size_t)(k0 + BK) * DD);
        }

        #pragma unroll
        for (int kk = 0; kk < BK; kk += 16) {
            wmma::fragment<wmma::matrix_a, 16, 16, 16, __half, wmma::row_major> af[2];
            wmma::fragment<wmma::matrix_b, 16, 16, 16, __half, wmma::row_major> bf[4];
            #pragma unroll
            for (int i = 0; i < 2; i++)
                wmma::load_matrix_sync(af[i], As + (wm * 32 + 16 * i) * LDA + kk, LDA);
            #pragma unroll
            for (int j = 0; j < 4; j++)
                wmma::load_matrix_sync(bf[j], Bs + kk * LDB + wn * 64 + 16 * j, LDB);
            #pragma unroll
            for (int i = 0; i < 2; i++)
                #pragma unroll
                for (int j = 0; j < 4; j++)
                    wmma::mma_sync(acc[i][j], af[i], bf[j], acc[i][j]);
        }
        __syncthreads();
    }

    #pragma unroll
    for (int i = 0; i < 2; i++) {
        #pragma unroll
        for (int j = 0; j < 4; j++) {
            wmma::store_matrix_sync(&stage[warp][0], acc[i][j], LDS_STAGE,
                                    wmma::mem_row_major);
            __syncwarp();
            const int r = lane >> 1, c = (lane & 1) * 8;
            const float* sp = &stage[warp][r * LDS_STAGE + c];
            __half2 h[4];
            #pragma unroll
            for (int x = 0; x < 4; x++)
                h[x] = __float22half2_rn(make_float2(sp[2 * x], sp[2 * x + 1]));
            __half* cp = C + (size_t)(block_row + wm * 32 + 16 * i + r) * DD
                       + block_col + wn * 64 + 16 * j + c;
            *(uint4*)cp = *(uint4*)h;
            __syncwarp();
        }
    }
}

// ---------------- K2: edge scores in sorted order (q-row L1 reuse) ----------
// One warp handles 4 consecutive SORTED edges x both batches (8 instances).
// Sorted by i0 -> a 256-thread block covers ~one i0-run (avg 32 edges): q row
// hits L1 after the first fetch. k rows remain random (L2).
__device__ __forceinline__ float hdot8_h2(uint4 q, uint4 k) {
    const __half2* qh = (const __half2*)&q;
    const __half2* kh = (const __half2*)&k;
    __half2 acc = __hmul2(qh[0], kh[0]);
    acc = __hfma2(qh[1], kh[1], acc);
    acc = __hfma2(qh[2], kh[2], acc);
    acc = __hfma2(qh[3], kh[3], acc);
    return __low2float(acc) + __high2float(acc);
}

__global__ void __launch_bounds__(256)
edge_sorted_kernel(float* __restrict__ out) {
    const int warp = (blockIdx.x * blockDim.x + threadIdx.x) >> 5;
    const int lane = threadIdx.x & 31;
    // grid exact: MM/4 = 80000 warps

    int mv = 0;
    if (lane < 4) mv = g_perm[warp * 4 + lane];

    #pragma unroll
    for (int t = 0; t < 4; t++) {
        const int m  = __shfl_sync(0xffffffffu, mv, t);
        const int i0 = g_mask32[m];
        const int i1 = g_mask32[MM + m];

        #pragma unroll
        for (int b = 0; b < BB; b++) {
            const uint4* q4 = (const uint4*)(g_qh + ((size_t)b * NN + i0) * DD);
            const uint4* k4 = (const uint4*)(g_kh + ((size_t)b * NN + i1) * DD);

            float p = hdot8_h2(q4[lane], k4[lane]);
            p += __shfl_down_sync(0xffffffffu, p, 2, 4);
            p += __shfl_down_sync(0xffffffffu, p, 1, 4);

            float e = 0.0f;
            if ((lane & 3) == 0) {
                e = __expf(p * 0.0625f);                       // / sqrt(256)
                out[((size_t)b * MM + m) * HH + (lane >> 2)] = e;
            }

            float4 vv;
            vv.x = __shfl_sync(0xffffffffu, e, (lane & 16) + 0);
            vv.y = __shfl_sync(0xffffffffu, e, (lane & 16) + 4);
            vv.z = __shfl_sync(0xffffffffu, e, (lane & 16) + 8);
            vv.w = __shfl_sync(0xffffffffu, e, (lane & 16) + 12);

            if ((lane & 15) == 0) {
                float* segp = g_seg + ((size_t)b * NN + i0) * HH + (lane >> 2);
                asm volatile("red.global.add.v4.f32 [%0], {%1, %2, %3, %4};"
                             :: "l"(segp), "f"(vv.x), "f"(vv.y), "f"(vv.z), "f"(vv.w)
                             : "memory");
            }
        }
    }
}

// ---------------- K3: out = e / (seg[idx] + 1e-16) in place ------------------
__global__ void __launch_bounds__(256)
normalize_kernel(float* __restrict__ e) {
    const int t = blockIdx.x * blockDim.x + threadIdx.x;
    if (t >= TOTAL_E) return;
    const int b = t / MM;
    const int m = t - b * MM;
    const int i0 = g_mask32[m];

    const float4* segp = (const float4*)(g_seg + ((size_t)b * NN + i0) * HH);
    float4 s0 = segp[0], s1 = segp[1];

    const size_t base = (size_t)t * HH;
    float4 e0 = *(float4*)(e + base);
    float4 e1 = *(float4*)(e + base + 4);

    e0.x /= (s0.x + 1e-16f);
    e0.y /= (s0.y + 1e-16f);
    e0.z /= (s0.z + 1e-16f);
    e0.w /= (s0.w + 1e-16f);
    e1.x /= (s1.x + 1e-16f);
    e1.y /= (s1.y + 1e-16f);
    e1.z /= (s1.z + 1e-16f);
    e1.w /= (s1.w + 1e-16f);

    *(float4*)(e + base)     = e0;
    *(float4*)(e + base + 4) = e1;
}

// ---------------- launch ----------------------------------------------------
extern "C" void kernel_launch(void* const* d_in, const int* in_sizes, int n_in,
                              void* d_out, int out_size) {
    const float* x_q  = (const float*)d_in[0];
    const float* x_k  = (const float*)d_in[1];
    const void*  mask = (const void*)d_in[2];
    const float* w_q  = (const float*)d_in[3];
    const float* w_k  = (const float*)d_in[4];
    float* out = (float*)d_out;

    // pre: mask dtype detect + normalize (+ zero seg/hist), weight convert
    detect_mask_kernel<<<1, 256>>>((const unsigned*)mask);
    convert_mask_kernel<<<(2 * MM + 255) / 256, 256>>>(mask);
    convert_weights_kernel<<<(2 * DD * DD / 8 + 255) / 256, 256>>>(w_q, w_k);

    // counting sort of edges by i0
    hist_kernel<<<(MM + 255) / 256, 256>>>();
    prefix_kernel<<<1, 256>>>();
    scatter_kernel<<<(MM + 255) / 256, 256>>>();

    // GEMM (fp32 A fused-convert, tensor cores)
    {
        dim3 grid(MPAD / 128, DD / 128, 2);
        gemm_wmma_kernel<<<grid, 256>>>(x_q, x_k);
    }
    // fused edge scores + exp + segment scatter, sorted order
    {
        int warps = MM / 4;                       // 80000
        edge_sorted_kernel<<<warps / 8, 256>>>(out);
    }
    // normalize
    {
        int blocks = (TOTAL_E + 255) / 256;
        normalize_kernel<<<blocks, 256>>>(out);
    }
}